// round 3
// baseline (speedup 1.0000x reference)
#include <cuda_runtime.h>

#define T_SAMPLES 8388608
#define NFFT 512
#define HOP 128
#define PAD 256
#define NFRAMES 65537          // 1 + (T + 2*PAD - NFFT)/HOP
#define K_BINS 257
#define FPB 128                // frames per block
#define NBLK 513               // ceil(NFRAMES / FPB)
#define NWARP 16
#define SUBF 8                 // frames per warp subchunk
#define BLK_SPAN (FPB * HOP)   // 16384
#define ACC_SPAN (SUBF * HOP + (NFFT - HOP))  // 1408
#define OVER (NFFT - HOP)      // 384
#define T_OUT (T_SAMPLES + 2 * PAD)
#define DECAYF 0.999f
#define PI_D 3.14159265358979323846

// ---------------- small global scratch (no big arrays anymore) ----------------
__device__ float  g_sub[NBLK * NWARP * K_BINS];   // per-subchunk inclusive summaries (~8.4 MB)
__device__ float  g_blk[NBLK * K_BINS];           // per-block inclusive summaries
__device__ float  g_blkpref[NBLK * K_BINS];       // cross-block exclusive prefixes
__device__ float  g_head[NBLK * OVER];            // block-boundary partial sums
__device__ float  g_tail[NBLK * OVER];
__device__ float2 g_W512[512];
__device__ float  g_win[512];
__device__ float  g_D8, g_D128;

__device__ __forceinline__ float2 cmul(float2 a, float2 b) {
    return make_float2(a.x * b.x - a.y * b.y, a.x * b.y + a.y * b.x);
}
__device__ __forceinline__ float2 csub(float2 a, float2 b) {
    return make_float2(a.x - b.x, a.y - b.y);
}
__device__ __forceinline__ float2 cadd(float2 a, float2 b) {
    return make_float2(a.x + b.x, a.y + b.y);
}
__device__ __forceinline__ int brev8(int x) { return (int)(__brev((unsigned)x) >> 24); }

// ---------------- tables ----------------
__global__ void init_tables() {
    int i = threadIdx.x;  // 512 threads
    double ang = -2.0 * PI_D * (double)i / 512.0;
    g_W512[i] = make_float2((float)cos(ang), (float)sin(ang));
    g_win[i]  = (float)(0.5 * (1.0 - cos(2.0 * PI_D * (double)i / 512.0)));
    if (i == 0) {
        g_D8   = (float)pow((double)DECAYF, 8.0);
        g_D128 = (float)pow((double)DECAYF, 128.0);
    }
}

// ---------------- warp-level 256-pt complex FFT (DIF radix-2) ----------------
// reg j (0..7), lane l holds x[32*j + l]; output reg j lane l holds X[brev8(32*j+l)].
__device__ __forceinline__ float2 bfly(float2 v, int m, float2 tw, int lane) {
    float2 o;
    o.x = __shfl_xor_sync(0xffffffffu, v.x, m);
    o.y = __shfl_xor_sync(0xffffffffu, v.y, m);
    float2 s = cadd(v, o);
    float2 d = csub(o, v);
    float2 dm = cmul(d, tw);
    return (lane & m) ? dm : s;
}

__device__ __forceinline__ void warp_fft256(float2 r[8], int lane, const float2* s_W) {
#pragma unroll
    for (int j = 0; j < 4; j++) {
        float2 a = r[j], b = r[j + 4];
        float2 w = s_W[2 * (32 * j + lane)];
        r[j] = cadd(a, b);
        r[j + 4] = cmul(csub(a, b), w);
    }
#pragma unroll
    for (int half = 0; half < 2; half++) {
#pragma unroll
        for (int j = 0; j < 2; j++) {
            int lo = half * 4 + j;
            float2 a = r[lo], b = r[lo + 2];
            float2 w = s_W[4 * (32 * j + lane)];
            r[lo] = cadd(a, b);
            r[lo + 2] = cmul(csub(a, b), w);
        }
    }
    {
        float2 w = s_W[8 * lane];
#pragma unroll
        for (int q = 0; q < 4; q++) {
            int lo = 2 * q;
            float2 a = r[lo], b = r[lo + 1];
            r[lo] = cadd(a, b);
            r[lo + 1] = cmul(csub(a, b), w);
        }
    }
    {
        float2 tw = s_W[16 * (lane & 15)];
#pragma unroll
        for (int j = 0; j < 8; j++) r[j] = bfly(r[j], 16, tw, lane);
    }
    {
        float2 tw = s_W[32 * (lane & 7)];
#pragma unroll
        for (int j = 0; j < 8; j++) r[j] = bfly(r[j], 8, tw, lane);
    }
    {
        float2 tw = s_W[64 * (lane & 3)];
#pragma unroll
        for (int j = 0; j < 8; j++) r[j] = bfly(r[j], 4, tw, lane);
    }
    {
        float2 tw = (lane & 1) ? make_float2(0.0f, -1.0f) : make_float2(1.0f, 0.0f);
#pragma unroll
        for (int j = 0; j < 8; j++) r[j] = bfly(r[j], 2, tw, lane);
    }
    {
        float2 tw = make_float2(1.0f, 0.0f);
#pragma unroll
        for (int j = 0; j < 8; j++) r[j] = bfly(r[j], 1, tw, lane);
    }
}

// ---------------- shared helpers ----------------
__device__ __forceinline__ void load_frame(const float* __restrict__ x, int f, int lane,
                                           const float* s_win, float2 r[8]) {
    int p0 = f * HOP - PAD;
    if (p0 >= 0 && p0 + NFFT <= T_SAMPLES) {
        const float2* xv = (const float2*)(x + p0);
#pragma unroll
        for (int j = 0; j < 8; j++) {
            int k = 32 * j + lane;
            float2 v = xv[k];
            r[j] = make_float2(v.x * s_win[2 * k], v.y * s_win[2 * k + 1]);
        }
    } else {
#pragma unroll
        for (int j = 0; j < 8; j++) {
            int k = 32 * j + lane;
            int pa = p0 + 2 * k, pb = pa + 1;
            if (pa < 0) pa = -pa; else if (pa >= T_SAMPLES) pa = 2 * T_SAMPLES - 2 - pa;
            if (pb < 0) pb = -pb; else if (pb >= T_SAMPLES) pb = 2 * T_SAMPLES - 2 - pb;
            r[j] = make_float2(x[pa] * s_win[2 * k], x[pb] * s_win[2 * k + 1]);
        }
    }
}

__device__ __forceinline__ float2 untwiddle(const float2* Z, const float2* W, int k) {
    int km = (256 - k) & 255;
    float2 zk = Z[k & 255];
    float2 zm = Z[km];
    float2 ze = make_float2(0.5f * (zk.x + zm.x), 0.5f * (zk.y - zm.y));
    float2 d  = make_float2(0.5f * (zk.x - zm.x), 0.5f * (zk.y + zm.y));
    float2 mid = make_float2(d.y, -d.x);          // -i * d
    float2 tw = W[k & 511];                       // k=256 -> (-1,0) handled via W[256]
    float2 tw2 = (k == 256) ? make_float2(-1.0f, 0.0f) : tw;
    float2 wm = cmul((k == 256) ? tw2 : tw, mid);
    return make_float2(ze.x + wm.x, ze.y + wm.y);
}

// ---------------- smem layouts ----------------
struct SmemA {
    float2 W[512];
    float  win[512];
    float2 Z[NWARP][256];
    float  sub[NWARP][K_BINS];
};
struct SmemB {
    float2 W[512];
    float  win[512];
    float2 Z[NWARP][256];
    float2 S[NWARP][K_BINS + 1];
    float  sub[NWARP][K_BINS];
    float  acc[NWARP][ACC_SPAN];
};

// ---------------- phase A: FFT + subchunk/block running-max summaries ----------------
__global__ __launch_bounds__(512, 1) void phaseA(const float* __restrict__ x) {
    extern __shared__ char raw[];
    SmemA* sm = (SmemA*)raw;
    int t = threadIdx.x, lane = t & 31, w = t >> 5, b = blockIdx.x;
    { int i = t; sm->W[i] = g_W512[i]; sm->win[i] = g_win[i]; }  // 512 threads, 512 entries
    __syncthreads();

    float r9[9];
#pragma unroll
    for (int u = 0; u < 9; u++) r9[u] = 0.0f;

    int f0 = b * FPB + w * SUBF;
    for (int i = 0; i < SUBF; i++) {
        int f = f0 + i;
        if (f >= NFRAMES) break;
        float2 r[8];
        load_frame(x, f, lane, sm->win, r);
        warp_fft256(r, lane, sm->W);
#pragma unroll
        for (int j = 0; j < 8; j++) sm->Z[w][brev8(32 * j + lane)] = r[j];
        __syncwarp();
#pragma unroll
        for (int u = 0; u < 9; u++) {
            int k = lane + 32 * u;
            if (k <= 256) {
                float2 X = untwiddle(sm->Z[w], sm->W, k);
                float m = sqrtf(X.x * X.x + X.y * X.y);
                r9[u] = fmaxf(DECAYF * r9[u], m);
            }
        }
        __syncwarp();
    }
#pragma unroll
    for (int u = 0; u < 9; u++) {
        int k = lane + 32 * u;
        if (k <= 256) {
            sm->sub[w][k] = r9[u];
            g_sub[(b * NWARP + w) * K_BINS + k] = r9[u];
        }
    }
    __syncthreads();
    if (t < K_BINS) {
        float D8 = g_D8;
        float B = 0.0f;
#pragma unroll
        for (int j = 0; j < NWARP; j++) B = fmaxf(D8 * B, sm->sub[j][t]);
        g_blk[b * K_BINS + t] = B;
    }
}

// ---------------- mid: cross-block exclusive max-affine scan ----------------
__global__ __launch_bounds__(288) void midscan() {
    int k = threadIdx.x;
    if (k >= K_BINS) return;
    float D128 = g_D128;
    float carry = 0.0f;
    int b = 0;
    for (; b + 16 <= NBLK; b += 16) {
        float v[16];
#pragma unroll
        for (int u = 0; u < 16; u++) v[u] = g_blk[(b + u) * K_BINS + k];
#pragma unroll
        for (int u = 0; u < 16; u++) {
            g_blkpref[(b + u) * K_BINS + k] = carry;
            carry = fmaxf(D128 * carry, v[u]);
        }
    }
    for (; b < NBLK; b++) {
        g_blkpref[b * K_BINS + k] = carry;
        carry = fmaxf(D128 * carry, g_blk[b * K_BINS + k]);
    }
}

// ---------------- phase B: recompute FFT, gain, inverse FFT, OLA, normalize ----------------
__global__ __launch_bounds__(512, 1) void phaseB(const float* __restrict__ x,
                                                 float* __restrict__ out) {
    extern __shared__ char raw[];
    SmemB* sm = (SmemB*)raw;
    int t = threadIdx.x, lane = t & 31, w = t >> 5, b = blockIdx.x;
    { int i = t; sm->W[i] = g_W512[i]; sm->win[i] = g_win[i]; }
    for (int i = t; i < NWARP * K_BINS; i += 512)
        ((float*)sm->sub)[i] = g_sub[b * NWARP * K_BINS + i];
    for (int i = t; i < NWARP * ACC_SPAN; i += 512)
        ((float*)sm->acc)[i] = 0.0f;
    __syncthreads();

    float D8 = g_D8;
    float r9[9];
#pragma unroll
    for (int u = 0; u < 9; u++) {
        int k = lane + 32 * u;
        float p = 0.0f;
        if (k <= 256) {
            p = g_blkpref[b * K_BINS + k];
            for (int j = 0; j < w; j++) p = fmaxf(D8 * p, sm->sub[j][k]);
        }
        r9[u] = p;
    }

    int f0 = b * FPB + w * SUBF;
    const float scale = 1.0f / 256.0f;
    for (int i = 0; i < SUBF; i++) {
        int f = f0 + i;
        if (f >= NFRAMES) break;
        float2 r[8];
        load_frame(x, f, lane, sm->win, r);
        warp_fft256(r, lane, sm->W);
#pragma unroll
        for (int j = 0; j < 8; j++) sm->Z[w][brev8(32 * j + lane)] = r[j];
        __syncwarp();
#pragma unroll
        for (int u = 0; u < 9; u++) {
            int k = lane + 32 * u;
            if (k <= 256) {
                float2 X = untwiddle(sm->Z[w], sm->W, k);
                float m2 = X.x * X.x + X.y * X.y;
                float m = sqrtf(m2);
                float rr = fmaxf(DECAYF * r9[u], m);
                r9[u] = rr;
                float g = m2 / (fmaxf(0.5f * rr * rr, 1e-8f) + m2);
                sm->S[w][k] = make_float2(g * X.x, g * X.y);
            }
        }
        __syncwarp();
        // inverse: repack gained rfft bins -> conj 256-pt spectrum
#pragma unroll
        for (int j = 0; j < 8; j++) {
            int k = 32 * j + lane;
            float2 xk = sm->S[w][k];
            float2 xm = sm->S[w][256 - k];
            float2 ze = make_float2(0.5f * (xk.x + xm.x), 0.5f * (xk.y - xm.y));
            float2 d  = make_float2(0.5f * (xk.x - xm.x), 0.5f * (xk.y + xm.y));
            float2 tw = sm->W[k];
            float2 zo = cmul(make_float2(tw.x, -tw.y), d);
            r[j] = make_float2(ze.x - zo.y, -(ze.y + zo.x));
        }
        warp_fft256(r, lane, sm->W);
        // accumulate windowed time frame into warp-private OLA buffer
        float* acc = sm->acc[w] + i * HOP;
#pragma unroll
        for (int j = 0; j < 8; j++) {
            int pos = brev8(32 * j + lane);
            int n = 2 * pos;
            float2* a2 = (float2*)(acc + n);
            float2 cur = *a2;
            cur.x += r[j].x * sm->win[n] * scale;
            cur.y -= r[j].y * sm->win[n + 1] * scale;
            *a2 = cur;
        }
        __syncwarp();
    }
    __syncthreads();

    // combine warp regions & write normalized interior output
    int t0 = b * BLK_SPAN;
    for (int s = t; s < BLK_SPAN; s += 512) {
        int wo = s >> 10;
        int off = s & 1023;
        float val = sm->acc[wo][off];
        if (off < OVER && wo > 0) val += sm->acc[wo - 1][1024 + off];
        if (s < OVER) {
            g_head[b * OVER + s] = val;
        } else {
            int tt = t0 + s;
            if (tt >= PAD && tt < PAD + T_SAMPLES) {
                int fmax_ = tt >> 7; if (fmax_ > NFRAMES - 1) fmax_ = NFRAMES - 1;
                int fmin_ = (tt - OVER) >> 7; if (fmin_ < 0) fmin_ = 0;
                float ws = 0.0f;
                for (int fr = fmin_; fr <= fmax_; fr++) {
                    float wv = sm->win[tt - (fr << 7)];
                    ws += wv * wv;
                }
                out[tt - PAD] = val / fmaxf(ws, 1e-11f);
            }
        }
    }
    // export tail partials (contributions to next block's head window)
    if (t < OVER) g_tail[b * OVER + t] = sm->acc[NWARP - 1][1024 + t];
}

// ---------------- fixup: block-boundary samples ----------------
__global__ __launch_bounds__(384) void fixup(float* __restrict__ out) {
    int b = blockIdx.x;
    int i = threadIdx.x;
    int tt = b * BLK_SPAN + i;
    float val = g_head[b * OVER + i] + (b > 0 ? g_tail[(b - 1) * OVER + i] : 0.0f);
    if (tt >= PAD && tt < PAD + T_SAMPLES) {
        int fmax_ = tt >> 7; if (fmax_ > NFRAMES - 1) fmax_ = NFRAMES - 1;
        int fmin_ = (tt - OVER) >> 7; if (fmin_ < 0) fmin_ = 0;
        float ws = 0.0f;
        for (int fr = fmin_; fr <= fmax_; fr++) {
            float wv = g_win[tt - (fr << 7)];
            ws += wv * wv;
        }
        out[tt - PAD] = val / fmaxf(ws, 1e-11f);
    }
}

// ---------------- launch ----------------
extern "C" void kernel_launch(void* const* d_in, const int* in_sizes, int n_in,
                              void* d_out, int out_size) {
    const float* x = (const float*)d_in[0];
    float* out = (float*)d_out;

    static bool attr_done = false;
    if (!attr_done) {
        cudaFuncSetAttribute(phaseA, cudaFuncAttributeMaxDynamicSharedMemorySize,
                             (int)sizeof(SmemA));
        cudaFuncSetAttribute(phaseB, cudaFuncAttributeMaxDynamicSharedMemorySize,
                             (int)sizeof(SmemB));
        attr_done = true;
    }

    init_tables<<<1, 512>>>();
    phaseA<<<NBLK, 512, sizeof(SmemA)>>>(x);
    midscan<<<1, 288>>>();
    phaseB<<<NBLK, 512, sizeof(SmemB)>>>(x, out);
    fixup<<<NBLK, 384>>>(out);
}

// round 5
// speedup vs baseline: 2.0388x; 2.0388x over previous
#include <cuda_runtime.h>

#define T_SAMPLES 8388608
#define NFFT 512
#define HOP 128
#define PAD 256
#define NFRAMES 65537          // 1 + (T + 2*PAD - NFFT)/HOP
#define K_BINS 257
#define FPB 128                // frames per block
#define NBLK 513               // ceil(NFRAMES / FPB)
#define NWARP 16
#define SUBF 8                 // frames per warp subchunk
#define BLK_SPAN (FPB * HOP)   // 16384
#define ACC_SPAN (SUBF * HOP + (NFFT - HOP))  // 1408 floats
#define OVER (NFFT - HOP)      // 384
#define DECAYF 0.999f
#define PI_D 3.14159265358979323846

// XOR swizzle: kills bank conflicts on bit-reversed float2 scatters/gathers.
#define SWZ(p) ((p) ^ (((p) >> 4) & 0x0F))

// ---------------- small global scratch ----------------
__device__ float  g_sub[NBLK * NWARP * K_BINS];   // per-subchunk inclusive summaries
__device__ float  g_blk[NBLK * K_BINS];           // per-block inclusive summaries
__device__ float  g_blkpref[NBLK * K_BINS];       // cross-block exclusive prefixes
__device__ float  g_head[NBLK * OVER];
__device__ float  g_tail[NBLK * OVER];
__device__ float2 g_W512[512];
__device__ float  g_win[512];
__device__ float  g_D8, g_D128;

__device__ __forceinline__ float2 cmul(float2 a, float2 b) {
    return make_float2(a.x * b.x - a.y * b.y, a.x * b.y + a.y * b.x);
}
__device__ __forceinline__ float2 csub(float2 a, float2 b) {
    return make_float2(a.x - b.x, a.y - b.y);
}
__device__ __forceinline__ float2 cadd(float2 a, float2 b) {
    return make_float2(a.x + b.x, a.y + b.y);
}
__device__ __forceinline__ int brev8(int x) { return (int)(__brev((unsigned)x) >> 24); }

// ---------------- tables ----------------
__global__ void init_tables() {
    int i = threadIdx.x;  // 512 threads
    double ang = -2.0 * PI_D * (double)i / 512.0;
    g_W512[i] = make_float2((float)cos(ang), (float)sin(ang));
    g_win[i]  = (float)(0.5 * (1.0 - cos(2.0 * PI_D * (double)i / 512.0)));
    if (i == 0) {
        g_D8   = (float)pow((double)DECAYF, 8.0);
        g_D128 = (float)pow((double)DECAYF, 128.0);
    }
}

// ---------------- warp-level 256-pt complex FFT (DIF radix-2) ----------------
// reg j (0..7), lane l holds x[32*j + l]; output reg j lane l holds X[brev8(32*j+l)].
__device__ __forceinline__ float2 bfly(float2 v, int m, float2 tw, int lane) {
    float2 o;
    o.x = __shfl_xor_sync(0xffffffffu, v.x, m);
    o.y = __shfl_xor_sync(0xffffffffu, v.y, m);
    float2 s = cadd(v, o);
    float2 d = csub(o, v);
    float2 dm = cmul(d, tw);
    return (lane & m) ? dm : s;
}

__device__ __forceinline__ void warp_fft256(float2 r[8], int lane, const float2* s_W) {
#pragma unroll
    for (int j = 0; j < 4; j++) {
        float2 a = r[j], b = r[j + 4];
        float2 w = s_W[2 * (32 * j + lane)];
        r[j] = cadd(a, b);
        r[j + 4] = cmul(csub(a, b), w);
    }
#pragma unroll
    for (int half = 0; half < 2; half++) {
#pragma unroll
        for (int j = 0; j < 2; j++) {
            int lo = half * 4 + j;
            float2 a = r[lo], b = r[lo + 2];
            float2 w = s_W[4 * (32 * j + lane)];
            r[lo] = cadd(a, b);
            r[lo + 2] = cmul(csub(a, b), w);
        }
    }
    {
        float2 w = s_W[8 * lane];
#pragma unroll
        for (int q = 0; q < 4; q++) {
            int lo = 2 * q;
            float2 a = r[lo], b = r[lo + 1];
            r[lo] = cadd(a, b);
            r[lo + 1] = cmul(csub(a, b), w);
        }
    }
    {
        float2 tw = s_W[16 * (lane & 15)];
#pragma unroll
        for (int j = 0; j < 8; j++) r[j] = bfly(r[j], 16, tw, lane);
    }
    {
        float2 tw = s_W[32 * (lane & 7)];
#pragma unroll
        for (int j = 0; j < 8; j++) r[j] = bfly(r[j], 8, tw, lane);
    }
    {
        float2 tw = s_W[64 * (lane & 3)];
#pragma unroll
        for (int j = 0; j < 8; j++) r[j] = bfly(r[j], 4, tw, lane);
    }
    {
        float2 tw = (lane & 1) ? make_float2(0.0f, -1.0f) : make_float2(1.0f, 0.0f);
#pragma unroll
        for (int j = 0; j < 8; j++) r[j] = bfly(r[j], 2, tw, lane);
    }
    {
        float2 tw = make_float2(1.0f, 0.0f);
#pragma unroll
        for (int j = 0; j < 8; j++) r[j] = bfly(r[j], 1, tw, lane);
    }
}

// ---------------- shared helpers ----------------
__device__ __forceinline__ void load_frame(const float* __restrict__ x, int f, int lane,
                                           const float2* s_win2, float2 r[8]) {
    int p0 = f * HOP - PAD;
    if (p0 >= 0 && p0 + NFFT <= T_SAMPLES) {
        const float2* xv = (const float2*)(x + p0);
#pragma unroll
        for (int j = 0; j < 8; j++) {
            int k = 32 * j + lane;
            float2 v = xv[k];
            float2 w2 = s_win2[k];
            r[j] = make_float2(v.x * w2.x, v.y * w2.y);
        }
    } else {
#pragma unroll
        for (int j = 0; j < 8; j++) {
            int k = 32 * j + lane;
            int pa = p0 + 2 * k, pb = pa + 1;
            if (pa < 0) pa = -pa; else if (pa >= T_SAMPLES) pa = 2 * T_SAMPLES - 2 - pa;
            if (pb < 0) pb = -pb; else if (pb >= T_SAMPLES) pb = 2 * T_SAMPLES - 2 - pb;
            float2 w2 = s_win2[k];
            r[j] = make_float2(x[pa] * w2.x, x[pb] * w2.y);
        }
    }
}

// untwiddle packed-FFT output (swizzled smem) -> rfft bin X[k], k in [0,256]
__device__ __forceinline__ float2 untwiddle_swz(const float2* Zs, const float2* W, int k) {
    int ka = k & 255;
    int km = (256 - k) & 255;
    float2 zk = Zs[SWZ(ka)];
    float2 zm = Zs[SWZ(km)];
    float2 ze = make_float2(0.5f * (zk.x + zm.x), 0.5f * (zk.y - zm.y));
    float2 d  = make_float2(0.5f * (zk.x - zm.x), 0.5f * (zk.y + zm.y));
    float2 mid = make_float2(d.y, -d.x);          // -i * d
    float2 tw = (k == 256) ? make_float2(-1.0f, 0.0f) : W[k];
    float2 wm = cmul(tw, mid);
    return make_float2(ze.x + wm.x, ze.y + wm.y);
}

// ---------------- smem layouts ----------------
struct SmemA {
    float2 W[512];
    float2 win2[256];
    float2 Z[NWARP][256];
    float  sub[NWARP][K_BINS];
};
struct SmemB {
    float2 W[512];
    float2 win2[256];
    float2 Z[NWARP][256];
    float2 s256[NWARP];
    float  sub[NWARP][K_BINS];
    float2 acc[NWARP][ACC_SPAN / 2];   // 704 float2 per warp
};

// ---------------- phase A: FFT + subchunk/block running-max summaries ----------------
__global__ __launch_bounds__(512) void phaseA(const float* __restrict__ x) {
    extern __shared__ char raw[];
    SmemA* sm = (SmemA*)raw;
    int t = threadIdx.x, lane = t & 31, w = t >> 5, b = blockIdx.x;
    sm->W[t] = g_W512[t];
    if (t < 256) sm->win2[t] = make_float2(g_win[2 * t], g_win[2 * t + 1]);
    __syncthreads();

    float2* Zs = sm->Z[w];
    float r9[9];
#pragma unroll
    for (int u = 0; u < 9; u++) r9[u] = 0.0f;

    int f0 = b * FPB + w * SUBF;
    for (int i = 0; i < SUBF; i++) {
        int f = f0 + i;
        if (f >= NFRAMES) break;
        float2 r[8];
        load_frame(x, f, lane, sm->win2, r);
        warp_fft256(r, lane, sm->W);
#pragma unroll
        for (int j = 0; j < 8; j++) Zs[SWZ(brev8(32 * j + lane))] = r[j];
        __syncwarp();
#pragma unroll
        for (int u = 0; u < 9; u++) {
            int k = lane + 32 * u;
            if (k <= 256) {
                float2 X = untwiddle_swz(Zs, sm->W, k);
                float m = sqrtf(X.x * X.x + X.y * X.y);
                r9[u] = fmaxf(DECAYF * r9[u], m);
            }
        }
        __syncwarp();
    }
#pragma unroll
    for (int u = 0; u < 9; u++) {
        int k = lane + 32 * u;
        if (k <= 256) {
            sm->sub[w][k] = r9[u];
            g_sub[(b * NWARP + w) * K_BINS + k] = r9[u];
        }
    }
    __syncthreads();
    if (t < K_BINS) {
        float D8 = g_D8;
        float B = 0.0f;
#pragma unroll
        for (int j = 0; j < NWARP; j++) B = fmaxf(D8 * B, sm->sub[j][t]);
        g_blk[b * K_BINS + t] = B;
    }
}

// ---------------- mid: cross-block exclusive max-affine scan ----------------
__global__ __launch_bounds__(288) void midscan() {
    int k = threadIdx.x;
    if (k >= K_BINS) return;
    float D128 = g_D128;
    float carry = 0.0f;
    int b = 0;
    for (; b + 16 <= NBLK; b += 16) {
        float v[16];
#pragma unroll
        for (int u = 0; u < 16; u++) v[u] = g_blk[(b + u) * K_BINS + k];
#pragma unroll
        for (int u = 0; u < 16; u++) {
            g_blkpref[(b + u) * K_BINS + k] = carry;
            carry = fmaxf(D128 * carry, v[u]);
        }
    }
    for (; b < NBLK; b++) {
        g_blkpref[b * K_BINS + k] = carry;
        carry = fmaxf(D128 * carry, g_blk[b * K_BINS + k]);
    }
}

// ---------------- phase B: recompute FFT, gain, inverse FFT, OLA, normalize ----------------
__global__ __launch_bounds__(512) void phaseB(const float* __restrict__ x,
                                              float* __restrict__ out) {
    extern __shared__ char raw[];
    SmemB* sm = (SmemB*)raw;
    int t = threadIdx.x, lane = t & 31, w = t >> 5, b = blockIdx.x;
    sm->W[t] = g_W512[t];
    if (t < 256) sm->win2[t] = make_float2(g_win[2 * t], g_win[2 * t + 1]);
    for (int i = t; i < NWARP * K_BINS; i += 512)
        ((float*)sm->sub)[i] = g_sub[b * NWARP * K_BINS + i];
    for (int i = t; i < NWARP * (ACC_SPAN / 2); i += 512)
        ((float2*)sm->acc)[i] = make_float2(0.0f, 0.0f);
    __syncthreads();

    float2* Zs = sm->Z[w];
    float D8 = g_D8;
    float r9[9];
#pragma unroll
    for (int u = 0; u < 9; u++) {
        int k = lane + 32 * u;
        float p = 0.0f;
        if (k <= 256) {
            p = g_blkpref[b * K_BINS + k];
            for (int j = 0; j < w; j++) p = fmaxf(D8 * p, sm->sub[j][k]);
        }
        r9[u] = p;
    }

    int f0 = b * FPB + w * SUBF;
    const float scale = 1.0f / 256.0f;
    for (int i = 0; i < SUBF; i++) {
        int f = f0 + i;
        if (f >= NFRAMES) break;
        float2 r[8];
        load_frame(x, f, lane, sm->win2, r);
        warp_fft256(r, lane, sm->W);
#pragma unroll
        for (int j = 0; j < 8; j++) Zs[SWZ(brev8(32 * j + lane))] = r[j];
        __syncwarp();

        // untwiddle + gain into registers (all reads before any overwrite)
        float2 gs[9];
#pragma unroll
        for (int u = 0; u < 9; u++) {
            int k = lane + 32 * u;
            if (k <= 256) {
                float2 X = untwiddle_swz(Zs, sm->W, k);
                float m2 = X.x * X.x + X.y * X.y;
                float m = sqrtf(m2);
                float rr = fmaxf(DECAYF * r9[u], m);
                r9[u] = rr;
                float g = m2 / (fmaxf(0.5f * rr * rr, 1e-8f) + m2);
                gs[u] = make_float2(g * X.x, g * X.y);
            }
        }
        __syncwarp();
        // write gained bins back into Z (swizzled); bin 256 to scalar slot
#pragma unroll
        for (int u = 0; u < 9; u++) {
            int k = lane + 32 * u;
            if (k < 256) Zs[SWZ(k)] = gs[u];
            else if (k == 256) sm->s256[w] = gs[u];
        }
        __syncwarp();

        // repack gained rfft bins -> conj 256-pt spectrum (registers)
        float2 s256v = sm->s256[w];
#pragma unroll
        for (int j = 0; j < 8; j++) {
            int k = 32 * j + lane;
            float2 xk = Zs[SWZ(k)];
            int q = (256 - k) & 255;
            float2 xm = Zs[SWZ(q)];
            if (k == 0) xm = s256v;
            float2 ze = make_float2(0.5f * (xk.x + xm.x), 0.5f * (xk.y - xm.y));
            float2 d  = make_float2(0.5f * (xk.x - xm.x), 0.5f * (xk.y + xm.y));
            float2 tw = sm->W[k];
            float2 zo = cmul(make_float2(tw.x, -tw.y), d);
            r[j] = make_float2(ze.x - zo.y, -(ze.y + zo.x));
        }
        __syncwarp();

        warp_fft256(r, lane, sm->W);

        // stage time-domain pairs into Z (swizzled scatter, conflict-free)
#pragma unroll
        for (int j = 0; j < 8; j++) {
            int pos = brev8(32 * j + lane);
            Zs[SWZ(pos)] = make_float2(r[j].x, -r[j].y);
        }
        __syncwarp();

        // linear window+scale+accumulate into warp-private OLA buffer
        float2* acc2 = sm->acc[w] + i * (HOP / 2);
#pragma unroll
        for (int j = 0; j < 8; j++) {
            int p = 32 * j + lane;
            float2 v = Zs[SWZ(p)];
            float2 w2 = sm->win2[p];
            float2 cur = acc2[p];
            cur.x = fmaf(v.x * scale, w2.x, cur.x);
            cur.y = fmaf(v.y * scale, w2.y, cur.y);
            acc2[p] = cur;
        }
        __syncwarp();
    }
    __syncthreads();

    // combine warp regions & write normalized interior output.
    // Interior samples always have exactly 4 overlapping Hann frames:
    // sum win^2 = 1.5 (cos terms cancel over 4 quarter-period offsets).
    const float INV_NORM = 1.0f / 1.5f;
    int t0 = b * BLK_SPAN;
    const float* accf = (const float*)sm->acc;
    for (int s = t; s < BLK_SPAN; s += 512) {
        int wo = s >> 10;
        int off = s & 1023;
        float val = accf[wo * ACC_SPAN + off];
        if (off < OVER && wo > 0) val += accf[(wo - 1) * ACC_SPAN + 1024 + off];
        if (s < OVER) {
            g_head[b * OVER + s] = val;
        } else {
            int tt = t0 + s;
            if (tt >= PAD && tt < PAD + T_SAMPLES) out[tt - PAD] = val * INV_NORM;
        }
    }
    if (t < OVER) g_tail[b * OVER + t] = accf[(NWARP - 1) * ACC_SPAN + 1024 + t];
}

// ---------------- fixup: block-boundary samples (general win^2 loop) ----------------
__global__ __launch_bounds__(384) void fixup(float* __restrict__ out) {
    int b = blockIdx.x;
    int i = threadIdx.x;
    int tt = b * BLK_SPAN + i;
    float val = g_head[b * OVER + i] + (b > 0 ? g_tail[(b - 1) * OVER + i] : 0.0f);
    if (tt >= PAD && tt < PAD + T_SAMPLES) {
        int fmax_ = tt >> 7; if (fmax_ > NFRAMES - 1) fmax_ = NFRAMES - 1;
        int fmin_ = (tt - OVER) >> 7; if (fmin_ < 0) fmin_ = 0;
        float ws = 0.0f;
        for (int fr = fmin_; fr <= fmax_; fr++) {
            float wv = g_win[tt - (fr << 7)];
            ws += wv * wv;
        }
        out[tt - PAD] = val / fmaxf(ws, 1e-11f);
    }
}

// ---------------- launch ----------------
extern "C" void kernel_launch(void* const* d_in, const int* in_sizes, int n_in,
                              void* d_out, int out_size) {
    const float* x = (const float*)d_in[0];
    float* out = (float*)d_out;

    static bool attr_done = false;
    if (!attr_done) {
        cudaFuncSetAttribute(phaseA, cudaFuncAttributeMaxDynamicSharedMemorySize,
                             (int)sizeof(SmemA));
        cudaFuncSetAttribute(phaseB, cudaFuncAttributeMaxDynamicSharedMemorySize,
                             (int)sizeof(SmemB));
        attr_done = true;
    }

    init_tables<<<1, 512>>>();
    phaseA<<<NBLK, 512, sizeof(SmemA)>>>(x);
    midscan<<<1, 288>>>();
    phaseB<<<NBLK, 512, sizeof(SmemB)>>>(x, out);
    fixup<<<NBLK, 384>>>(out);
}

// round 6
// speedup vs baseline: 2.5715x; 1.2613x over previous
#include <cuda_runtime.h>

#define T_SAMPLES 8388608
#define NFFT 512
#define HOP 128
#define PAD 256
#define NFRAMES 65537          // 1 + (T + 2*PAD - NFFT)/HOP
#define NPAIR 129              // mirror pairs (k, 256-k), k = 0..128
#define FPB 64                 // frames per block
#define NBLKS 1025             // ceil(NFRAMES / FPB)
#define NWARP 16
#define SUBF 4                 // frames per warp subchunk
#define BLK_SPAN (FPB * HOP)   // 8192
#define ACC_SPAN (SUBF * HOP + (NFFT - HOP))  // 896 floats
#define OVER (NFFT - HOP)      // 384
#define NSUP 41                // superchunks: 1025 = 41 * 25
#define SUPLEN 25
#define DECAYF 0.999f
#define PI_D 3.14159265358979323846

// XOR swizzle: kills bank conflicts on bit-reversed float2 scatters/gathers.
#define SWZ(p) ((p) ^ (((p) >> 4) & 0x0F))

// ---------------- global scratch ----------------
__device__ float4 g_pair[(size_t)NFRAMES * NPAIR];      // (E, P) per mirror pair, ~135MB
__device__ float2 g_subP[NBLKS * NWARP * NPAIR];        // per-subchunk (rA, rB) summaries
__device__ float2 g_blkP[NBLKS * NPAIR];                // per-block inclusive summaries
__device__ float2 g_blkprefP[NBLKS * NPAIR];            // per-block exclusive prefixes
__device__ float2 g_supP[NSUP * NPAIR];                 // superchunk inclusive totals
__device__ float2 g_supprefP[NSUP * NPAIR];             // superchunk exclusive prefixes
__device__ float  g_head[NBLKS * OVER];
__device__ float  g_tail[NBLKS * OVER];
__device__ float2 g_W512[512];
__device__ float  g_win[512];
__device__ float  g_D4, g_D64, g_D1600;

__device__ __forceinline__ float2 cmul(float2 a, float2 b) {
    return make_float2(a.x * b.x - a.y * b.y, a.x * b.y + a.y * b.x);
}
__device__ __forceinline__ float2 csub(float2 a, float2 b) {
    return make_float2(a.x - b.x, a.y - b.y);
}
__device__ __forceinline__ float2 cadd(float2 a, float2 b) {
    return make_float2(a.x + b.x, a.y + b.y);
}
__device__ __forceinline__ int brev8(int x) { return (int)(__brev((unsigned)x) >> 24); }

// ---------------- tables ----------------
__global__ void init_tables() {
    int i = threadIdx.x;  // 512 threads
    double ang = -2.0 * PI_D * (double)i / 512.0;
    g_W512[i] = make_float2((float)cos(ang), (float)sin(ang));
    g_win[i]  = (float)(0.5 * (1.0 - cos(2.0 * PI_D * (double)i / 512.0)));
    if (i == 0) {
        g_D4    = (float)pow((double)DECAYF, 4.0);
        g_D64   = (float)pow((double)DECAYF, 64.0);
        g_D1600 = (float)pow((double)DECAYF, 1600.0);
    }
}

// ---------------- warp-level 256-pt complex FFT (DIF radix-2) ----------------
// reg j (0..7), lane l holds x[32*j + l]; output reg j lane l holds X[brev8(32*j+l)].
__device__ __forceinline__ float2 bfly(float2 v, int m, float2 tw, int lane) {
    float2 o;
    o.x = __shfl_xor_sync(0xffffffffu, v.x, m);
    o.y = __shfl_xor_sync(0xffffffffu, v.y, m);
    float2 s = cadd(v, o);
    float2 d = csub(o, v);
    float2 dm = cmul(d, tw);
    return (lane & m) ? dm : s;
}

__device__ __forceinline__ void warp_fft256(float2 r[8], int lane, const float2* s_W) {
#pragma unroll
    for (int j = 0; j < 4; j++) {
        float2 a = r[j], b = r[j + 4];
        float2 w = s_W[2 * (32 * j + lane)];
        r[j] = cadd(a, b);
        r[j + 4] = cmul(csub(a, b), w);
    }
#pragma unroll
    for (int half = 0; half < 2; half++) {
#pragma unroll
        for (int j = 0; j < 2; j++) {
            int lo = half * 4 + j;
            float2 a = r[lo], b = r[lo + 2];
            float2 w = s_W[4 * (32 * j + lane)];
            r[lo] = cadd(a, b);
            r[lo + 2] = cmul(csub(a, b), w);
        }
    }
    {
        float2 w = s_W[8 * lane];
#pragma unroll
        for (int q = 0; q < 4; q++) {
            int lo = 2 * q;
            float2 a = r[lo], b = r[lo + 1];
            r[lo] = cadd(a, b);
            r[lo + 1] = cmul(csub(a, b), w);
        }
    }
    {
        float2 tw = s_W[16 * (lane & 15)];
#pragma unroll
        for (int j = 0; j < 8; j++) r[j] = bfly(r[j], 16, tw, lane);
    }
    {
        float2 tw = s_W[32 * (lane & 7)];
#pragma unroll
        for (int j = 0; j < 8; j++) r[j] = bfly(r[j], 8, tw, lane);
    }
    {
        float2 tw = s_W[64 * (lane & 3)];
#pragma unroll
        for (int j = 0; j < 8; j++) r[j] = bfly(r[j], 4, tw, lane);
    }
    {
        float2 tw = (lane & 1) ? make_float2(0.0f, -1.0f) : make_float2(1.0f, 0.0f);
#pragma unroll
        for (int j = 0; j < 8; j++) r[j] = bfly(r[j], 2, tw, lane);
    }
    {
        float2 tw = make_float2(1.0f, 0.0f);
#pragma unroll
        for (int j = 0; j < 8; j++) r[j] = bfly(r[j], 1, tw, lane);
    }
}

// ---------------- shared helpers ----------------
__device__ __forceinline__ void load_frame(const float* __restrict__ x, int f, int lane,
                                           const float2* s_win2, float2 r[8]) {
    int p0 = f * HOP - PAD;
    if (p0 >= 0 && p0 + NFFT <= T_SAMPLES) {
        const float2* xv = (const float2*)(x + p0);
#pragma unroll
        for (int j = 0; j < 8; j++) {
            int k = 32 * j + lane;
            float2 v = xv[k];
            float2 w2 = s_win2[k];
            r[j] = make_float2(v.x * w2.x, v.y * w2.y);
        }
    } else {
#pragma unroll
        for (int j = 0; j < 8; j++) {
            int k = 32 * j + lane;
            int pa = p0 + 2 * k, pb = pa + 1;
            if (pa < 0) pa = -pa; else if (pa >= T_SAMPLES) pa = 2 * T_SAMPLES - 2 - pa;
            if (pb < 0) pb = -pb; else if (pb >= T_SAMPLES) pb = 2 * T_SAMPLES - 2 - pb;
            float2 w2 = s_win2[k];
            r[j] = make_float2(x[pa] * w2.x, x[pb] * w2.y);
        }
    }
}

// ---------------- smem layouts ----------------
struct SmemA {
    float2 W[512];
    float2 win2[256];
    float2 Z[NWARP][256];
    float2 subP[NWARP][NPAIR];
};
struct SmemB {
    float2 W[512];
    float2 win2[256];
    float2 Z[NWARP][256];
    float2 subP[NWARP][NPAIR];
    float2 acc[NWARP][ACC_SPAN / 2];   // 448 float2 per warp
};

// ---------------- phase A: FFT -> paired (E,P) spectrum + runmax summaries ----------------
__global__ __launch_bounds__(512) void phaseA(const float* __restrict__ x) {
    extern __shared__ char raw[];
    SmemA* sm = (SmemA*)raw;
    int t = threadIdx.x, lane = t & 31, w = t >> 5, b = blockIdx.x;
    sm->W[t] = g_W512[t];
    if (t < 256) sm->win2[t] = make_float2(g_win[2 * t], g_win[2 * t + 1]);
    __syncthreads();

    float2* Zs = sm->Z[w];
    float rA[5], rB[5];
#pragma unroll
    for (int u = 0; u < 5; u++) { rA[u] = 0.0f; rB[u] = 0.0f; }

    int f0 = b * FPB + w * SUBF;
    for (int i = 0; i < SUBF; i++) {
        int f = f0 + i;
        if (f >= NFRAMES) break;
        float2 r[8];
        load_frame(x, f, lane, sm->win2, r);
        warp_fft256(r, lane, sm->W);
#pragma unroll
        for (int j = 0; j < 8; j++) Zs[SWZ(brev8(32 * j + lane))] = r[j];
        __syncwarp();

        size_t base = (size_t)f * NPAIR;
#pragma unroll
        for (int u = 0; u < 5; u++) {
            int k = (u < 4) ? 32 * u + lane : 128;
            bool active = (u < 4) || (lane == 0);
            if (active) {
                float2 zk = Zs[SWZ(k)];
                float2 zm = Zs[SWZ((256 - k) & 255)];
                float2 E = make_float2(0.5f * (zk.x + zm.x), 0.5f * (zk.y - zm.y));
                float2 d = make_float2(0.5f * (zk.x - zm.x), 0.5f * (zk.y + zm.y));
                float2 mid = make_float2(d.y, -d.x);          // -i * d
                float2 P = cmul(sm->W[k], mid);
                g_pair[base + k] = make_float4(E.x, E.y, P.x, P.y);
                float ax = E.x + P.x, ay = E.y + P.y;
                float bx = E.x - P.x, by = E.y - P.y;
                rA[u] = fmaxf(DECAYF * rA[u], sqrtf(ax * ax + ay * ay));
                rB[u] = fmaxf(DECAYF * rB[u], sqrtf(bx * bx + by * by));
            }
        }
        __syncwarp();
    }
    // write subchunk summaries (always, even for idle warps -> zeros)
#pragma unroll
    for (int u = 0; u < 5; u++) {
        int k = (u < 4) ? 32 * u + lane : 128;
        bool active = (u < 4) || (lane == 0);
        if (active) {
            float2 s = make_float2(rA[u], rB[u]);
            sm->subP[w][k] = s;
            g_subP[(b * NWARP + w) * NPAIR + k] = s;
        }
    }
    __syncthreads();
    // block summary over 16 subchunks (float view width 2*NPAIR = 258)
    if (t < 2 * NPAIR) {
        float D4 = g_D4;
        const float* subF = (const float*)sm->subP;
        float B = 0.0f;
#pragma unroll
        for (int j = 0; j < NWARP; j++) B = fmaxf(D4 * B, subF[j * 2 * NPAIR + t]);
        ((float*)g_blkP)[b * 2 * NPAIR + t] = B;
    }
}

// ---------------- 3-level cross-block scan ----------------
__global__ __launch_bounds__(288) void midscanA() {
    int t = threadIdx.x;
    if (t >= 2 * NPAIR) return;
    int s = blockIdx.x;
    const float* blkF = (const float*)g_blkP;
    float D64 = g_D64;
    float v[SUPLEN];
#pragma unroll
    for (int j = 0; j < SUPLEN; j++) v[j] = blkF[(s * SUPLEN + j) * 2 * NPAIR + t];
    float carry = 0.0f;
#pragma unroll
    for (int j = 0; j < SUPLEN; j++) carry = fmaxf(D64 * carry, v[j]);
    ((float*)g_supP)[s * 2 * NPAIR + t] = carry;
}

__global__ __launch_bounds__(288) void midscanB() {
    int t = threadIdx.x;
    if (t >= 2 * NPAIR) return;
    const float* supF = (const float*)g_supP;
    float D1600 = g_D1600;
    float v[NSUP];
#pragma unroll
    for (int s = 0; s < NSUP; s++) v[s] = supF[s * 2 * NPAIR + t];
    float carry = 0.0f;
#pragma unroll
    for (int s = 0; s < NSUP; s++) {
        ((float*)g_supprefP)[s * 2 * NPAIR + t] = carry;
        carry = fmaxf(D1600 * carry, v[s]);
    }
}

__global__ __launch_bounds__(288) void midscanC() {
    int t = threadIdx.x;
    if (t >= 2 * NPAIR) return;
    int s = blockIdx.x;
    const float* blkF = (const float*)g_blkP;
    float D64 = g_D64;
    float v[SUPLEN];
#pragma unroll
    for (int j = 0; j < SUPLEN; j++) v[j] = blkF[(s * SUPLEN + j) * 2 * NPAIR + t];
    float carry = ((const float*)g_supprefP)[s * 2 * NPAIR + t];
#pragma unroll
    for (int j = 0; j < SUPLEN; j++) {
        ((float*)g_blkprefP)[(s * SUPLEN + j) * 2 * NPAIR + t] = carry;
        carry = fmaxf(D64 * carry, v[j]);
    }
}

// ---------------- phase B: load pairs, gain+repack in regs, inverse FFT, OLA ----------------
__global__ __launch_bounds__(512) void phaseB(float* __restrict__ out) {
    extern __shared__ char raw[];
    SmemB* sm = (SmemB*)raw;
    int t = threadIdx.x, lane = t & 31, w = t >> 5, b = blockIdx.x;
    sm->W[t] = g_W512[t];
    if (t < 256) sm->win2[t] = make_float2(g_win[2 * t], g_win[2 * t + 1]);
    for (int i = t; i < NWARP * NPAIR; i += 512)
        ((float2*)sm->subP)[i] = g_subP[b * NWARP * NPAIR + i];
    for (int i = t; i < NWARP * (ACC_SPAN / 2); i += 512)
        ((float2*)sm->acc)[i] = make_float2(0.0f, 0.0f);
    __syncthreads();

    float2* Zs = sm->Z[w];
    float D4 = g_D4;
    float rA[5], rB[5];
#pragma unroll
    for (int u = 0; u < 5; u++) {
        int k = (u < 4) ? 32 * u + lane : 128;
        bool active = (u < 4) || (lane == 0);
        float2 p = make_float2(0.0f, 0.0f);
        if (active) {
            p = g_blkprefP[b * NPAIR + k];
            for (int j = 0; j < w; j++) {
                float2 sv = sm->subP[j][k];
                p.x = fmaxf(D4 * p.x, sv.x);
                p.y = fmaxf(D4 * p.y, sv.y);
            }
        }
        rA[u] = p.x; rB[u] = p.y;
    }

    int f0 = b * FPB + w * SUBF;
    const float scale = 1.0f / 256.0f;
    for (int i = 0; i < SUBF; i++) {
        int f = f0 + i;
        if (f >= NFRAMES) break;
        size_t base = (size_t)f * NPAIR;

        // load pair data first (MLP), then process
        float4 c[5];
#pragma unroll
        for (int u = 0; u < 5; u++) {
            int k = (u < 4) ? 32 * u + lane : 128;
            bool active = (u < 4) || (lane == 0);
            if (active) c[u] = g_pair[base + k];
        }

#pragma unroll
        for (int u = 0; u < 5; u++) {
            int k = (u < 4) ? 32 * u + lane : 128;
            bool active = (u < 4) || (lane == 0);
            if (active) {
                float2 E = make_float2(c[u].x, c[u].y);
                float2 P = make_float2(c[u].z, c[u].w);
                float ax = E.x + P.x, ay = E.y + P.y;
                float bx = E.x - P.x, by = E.y - P.y;
                float ma2 = ax * ax + ay * ay;
                float mb2 = bx * bx + by * by;
                float ra = fmaxf(DECAYF * rA[u], sqrtf(ma2)); rA[u] = ra;
                float rb = fmaxf(DECAYF * rB[u], sqrtf(mb2)); rB[u] = rb;
                float ga = ma2 / (fmaxf(0.5f * ra * ra, 1e-8f) + ma2);
                float gb = mb2 / (fmaxf(0.5f * rb * rb, 1e-8f) + mb2);
                float s = 0.5f * (ga + gb), md = 0.5f * (ga - gb);
                float2 ze = make_float2(s * E.x + md * P.x, s * E.y + md * P.y);
                float2 d2 = make_float2(md * E.x + s * P.x, md * E.y + s * P.y);
                float2 tw = sm->W[k];
                // zo = conj(W^k) * d2
                float2 zo = make_float2(tw.x * d2.x + tw.y * d2.y,
                                        tw.x * d2.y - tw.y * d2.x);
                // V[k] = conj(ze + i*zo); V[256-k] = ze - i*zo
                Zs[SWZ(k)] = make_float2(ze.x - zo.y, -(ze.y + zo.x));
                if (k >= 1 && k <= 127)
                    Zs[SWZ(256 - k)] = make_float2(ze.x + zo.y, ze.y - zo.x);
            }
        }
        __syncwarp();

        float2 r[8];
#pragma unroll
        for (int j = 0; j < 8; j++) r[j] = Zs[SWZ(32 * j + lane)];
        warp_fft256(r, lane, sm->W);

        // stage time-domain pairs into Z (swizzled scatter, conflict-free)
#pragma unroll
        for (int j = 0; j < 8; j++) {
            int pos = brev8(32 * j + lane);
            Zs[SWZ(pos)] = make_float2(r[j].x, -r[j].y);
        }
        __syncwarp();

        // linear window+scale+accumulate into warp-private OLA buffer
        float2* acc2 = sm->acc[w] + i * (HOP / 2);
#pragma unroll
        for (int j = 0; j < 8; j++) {
            int p = 32 * j + lane;
            float2 v = Zs[SWZ(p)];
            float2 w2 = sm->win2[p];
            float2 cur = acc2[p];
            cur.x = fmaf(v.x * scale, w2.x, cur.x);
            cur.y = fmaf(v.y * scale, w2.y, cur.y);
            acc2[p] = cur;
        }
        __syncwarp();
    }
    __syncthreads();

    // combine warp regions & write normalized interior output.
    // Interior: exactly 4 overlapping Hann frames -> sum win^2 = 1.5.
    const float INV_NORM = 1.0f / 1.5f;
    int t0 = b * BLK_SPAN;
    const float* accf = (const float*)sm->acc;
    for (int s = t; s < BLK_SPAN; s += 512) {
        int wo = s >> 9;          // 512 samples per warp region
        int off = s & 511;
        float val = accf[wo * ACC_SPAN + off];
        if (off < OVER && wo > 0) val += accf[(wo - 1) * ACC_SPAN + 512 + off];
        if (s < OVER) {
            g_head[b * OVER + s] = val;
        } else {
            int tt = t0 + s;
            if (tt >= PAD && tt < PAD + T_SAMPLES) out[tt - PAD] = val * INV_NORM;
        }
    }
    if (t < OVER) g_tail[b * OVER + t] = accf[(NWARP - 1) * ACC_SPAN + 512 + t];
}

// ---------------- fixup: block-boundary samples (general win^2 loop) ----------------
__global__ __launch_bounds__(384) void fixup(float* __restrict__ out) {
    int b = blockIdx.x;
    int i = threadIdx.x;
    int tt = b * BLK_SPAN + i;
    float val = g_head[b * OVER + i] + (b > 0 ? g_tail[(b - 1) * OVER + i] : 0.0f);
    if (tt >= PAD && tt < PAD + T_SAMPLES) {
        int fmax_ = tt >> 7; if (fmax_ > NFRAMES - 1) fmax_ = NFRAMES - 1;
        int fmin_ = (tt - OVER) >> 7; if (fmin_ < 0) fmin_ = 0;
        float ws = 0.0f;
        for (int fr = fmin_; fr <= fmax_; fr++) {
            float wv = g_win[tt - (fr << 7)];
            ws += wv * wv;
        }
        out[tt - PAD] = val / fmaxf(ws, 1e-11f);
    }
}

// ---------------- launch ----------------
extern "C" void kernel_launch(void* const* d_in, const int* in_sizes, int n_in,
                              void* d_out, int out_size) {
    const float* x = (const float*)d_in[0];
    float* out = (float*)d_out;

    static bool attr_done = false;
    if (!attr_done) {
        cudaFuncSetAttribute(phaseA, cudaFuncAttributeMaxDynamicSharedMemorySize,
                             (int)sizeof(SmemA));
        cudaFuncSetAttribute(phaseB, cudaFuncAttributeMaxDynamicSharedMemorySize,
                             (int)sizeof(SmemB));
        attr_done = true;
    }

    init_tables<<<1, 512>>>();
    phaseA<<<NBLKS, 512, sizeof(SmemA)>>>(x);
    midscanA<<<NSUP, 288>>>();
    midscanB<<<1, 288>>>();
    midscanC<<<NSUP, 288>>>();
    phaseB<<<NBLKS, 512, sizeof(SmemB)>>>(out);
    fixup<<<NBLKS, 384>>>(out);
}

// round 7
// speedup vs baseline: 3.0704x; 1.1940x over previous
#include <cuda_runtime.h>

#define T_SAMPLES 8388608
#define NFFT 512
#define HOP 128
#define PAD 256
#define NFRAMES 65537          // 1 + (T + 2*PAD - NFFT)/HOP
#define NPAIR 129              // mirror pairs (k, 256-k), k = 0..128
#define FPB 64                 // frames per block
#define NBLKS 1025             // ceil(NFRAMES / FPB)
#define NWARP 16
#define SUBF 4                 // frames per warp subchunk
#define BLK_SPAN (FPB * HOP)   // 8192
#define ACC_SPAN (SUBF * HOP + (NFFT - HOP))  // 896 floats
#define OVER (NFFT - HOP)      // 384
#define NSUP 41                // superchunks: 1025 = 41 * 25
#define SUPLEN 25
#define DECAYF 0.999f
#define PI_D 3.14159265358979323846

// XOR swizzle: kills bank conflicts on bit-reversed float2 scatters/gathers.
#define SWZ(p) ((p) ^ (((p) >> 4) & 0x0F))

// ---------------- global scratch ----------------
__device__ float4 g_pair[(size_t)NFRAMES * NPAIR];      // (E, P) per mirror pair, ~135MB
__device__ float2 g_subP[NBLKS * NWARP * NPAIR];        // per-subchunk (rA, rB) summaries
__device__ float2 g_blkP[NBLKS * NPAIR];                // per-block inclusive summaries
__device__ float2 g_blkprefP[NBLKS * NPAIR];            // per-block exclusive prefixes
__device__ float2 g_supP[NSUP * NPAIR];                 // superchunk inclusive totals
__device__ float2 g_supprefP[NSUP * NPAIR];             // superchunk exclusive prefixes
__device__ float  g_head[NBLKS * OVER];
__device__ float  g_tail[NBLKS * OVER];
__device__ float2 g_W512[512];
__device__ float  g_win[512];
__device__ float  g_D4, g_D64, g_D1600;

__device__ __forceinline__ float2 cmul(float2 a, float2 b) {
    return make_float2(a.x * b.x - a.y * b.y, a.x * b.y + a.y * b.x);
}
__device__ __forceinline__ float2 csub(float2 a, float2 b) {
    return make_float2(a.x - b.x, a.y - b.y);
}
__device__ __forceinline__ float2 cadd(float2 a, float2 b) {
    return make_float2(a.x + b.x, a.y + b.y);
}
__device__ __forceinline__ int brev8(int x) { return (int)(__brev((unsigned)x) >> 24); }

// ---------------- tables ----------------
__global__ void init_tables() {
    int i = threadIdx.x;  // 512 threads
    double ang = -2.0 * PI_D * (double)i / 512.0;
    g_W512[i] = make_float2((float)cos(ang), (float)sin(ang));
    g_win[i]  = (float)(0.5 * (1.0 - cos(2.0 * PI_D * (double)i / 512.0)));
    if (i == 0) {
        g_D4    = (float)pow((double)DECAYF, 4.0);
        g_D64   = (float)pow((double)DECAYF, 64.0);
        g_D1600 = (float)pow((double)DECAYF, 1600.0);
    }
}

// ---------------- warp-level 256-pt complex FFT (DIF radix-2, slim butterflies) ----------------
// reg j (0..7), lane l holds x[32*j + l]; output reg j lane l holds X[brev8(32*j+l)].
// Shuffle-stage butterfly: s = o + sgn*v (sgn=-1 on upper lane => o - v),
// then multiply by w_eff (= tw on upper lane, 1 on lower). sgn/w_eff hoisted per stage.
__device__ __forceinline__ void warp_fft256(float2 r[8], int lane, const float2* s_W) {
    // in-register stages (across regs)
#pragma unroll
    for (int j = 0; j < 4; j++) {
        float2 a = r[j], b = r[j + 4];
        float2 w = s_W[2 * (32 * j + lane)];
        r[j] = cadd(a, b);
        r[j + 4] = cmul(csub(a, b), w);
    }
#pragma unroll
    for (int half = 0; half < 2; half++) {
#pragma unroll
        for (int j = 0; j < 2; j++) {
            int lo = half * 4 + j;
            float2 a = r[lo], b = r[lo + 2];
            float2 w = s_W[4 * (32 * j + lane)];
            r[lo] = cadd(a, b);
            r[lo + 2] = cmul(csub(a, b), w);
        }
    }
    {
        float2 w = s_W[8 * lane];
#pragma unroll
        for (int q = 0; q < 4; q++) {
            int lo = 2 * q;
            float2 a = r[lo], b = r[lo + 1];
            r[lo] = cadd(a, b);
            r[lo + 1] = cmul(csub(a, b), w);
        }
    }
    // shuffle stages m = 16, 8, 4, 2 (generic), m = 1 (add/sub only)
#pragma unroll
    for (int sidx = 0; sidx < 4; sidx++) {
        const int m = 16 >> sidx;
        bool up = (lane & m) != 0;
        float sgn = up ? -1.0f : 1.0f;
        float2 tw = s_W[(256 / m) * (lane & (m - 1))];
        float2 w_eff = up ? tw : make_float2(1.0f, 0.0f);
#pragma unroll
        for (int j = 0; j < 8; j++) {
            float ox = __shfl_xor_sync(0xffffffffu, r[j].x, m);
            float oy = __shfl_xor_sync(0xffffffffu, r[j].y, m);
            float sx = fmaf(sgn, r[j].x, ox);
            float sy = fmaf(sgn, r[j].y, oy);
            r[j] = cmul(make_float2(sx, sy), w_eff);
        }
    }
    {
        float sgn = (lane & 1) ? -1.0f : 1.0f;
#pragma unroll
        for (int j = 0; j < 8; j++) {
            float ox = __shfl_xor_sync(0xffffffffu, r[j].x, 1);
            float oy = __shfl_xor_sync(0xffffffffu, r[j].y, 1);
            r[j] = make_float2(fmaf(sgn, r[j].x, ox), fmaf(sgn, r[j].y, oy));
        }
    }
}

// ---------------- shared helpers ----------------
__device__ __forceinline__ void load_frame(const float* __restrict__ x, int f, int lane,
                                           const float2* s_win2, float2 r[8]) {
    int p0 = f * HOP - PAD;
    if (p0 >= 0 && p0 + NFFT <= T_SAMPLES) {
        const float2* xv = (const float2*)(x + p0);
#pragma unroll
        for (int j = 0; j < 8; j++) {
            int k = 32 * j + lane;
            float2 v = xv[k];
            float2 w2 = s_win2[k];
            r[j] = make_float2(v.x * w2.x, v.y * w2.y);
        }
    } else {
#pragma unroll
        for (int j = 0; j < 8; j++) {
            int k = 32 * j + lane;
            int pa = p0 + 2 * k, pb = pa + 1;
            if (pa < 0) pa = -pa; else if (pa >= T_SAMPLES) pa = 2 * T_SAMPLES - 2 - pa;
            if (pb < 0) pb = -pb; else if (pb >= T_SAMPLES) pb = 2 * T_SAMPLES - 2 - pb;
            float2 w2 = s_win2[k];
            r[j] = make_float2(x[pa] * w2.x, x[pb] * w2.y);
        }
    }
}

// ---------------- smem layouts ----------------
struct SmemA {
    float2 W[512];
    float2 win2[256];
    float2 Z[NWARP][256];
    float2 subP[NWARP][NPAIR];
};
struct SmemB {
    float2 W[512];
    float2 win2[256];
    float2 Z[NWARP][256];
    float2 acc[NWARP][ACC_SPAN / 2];   // 448 float2 per warp
};

// ---------------- phase A: FFT -> paired (E,P) spectrum + runmax summaries ----------------
__global__ __launch_bounds__(512, 2) void phaseA(const float* __restrict__ x) {
    extern __shared__ char raw[];
    SmemA* sm = (SmemA*)raw;
    int t = threadIdx.x, lane = t & 31, w = t >> 5, b = blockIdx.x;
    sm->W[t] = g_W512[t];
    if (t < 256) sm->win2[t] = make_float2(g_win[2 * t], g_win[2 * t + 1]);
    __syncthreads();

    float2* Zs = sm->Z[w];
    float rA[5], rB[5];
#pragma unroll
    for (int u = 0; u < 5; u++) { rA[u] = 0.0f; rB[u] = 0.0f; }

    int f0 = b * FPB + w * SUBF;
    for (int i = 0; i < SUBF; i++) {
        int f = f0 + i;
        if (f >= NFRAMES) break;
        float2 r[8];
        load_frame(x, f, lane, sm->win2, r);
        warp_fft256(r, lane, sm->W);
#pragma unroll
        for (int j = 0; j < 8; j++) Zs[SWZ(brev8(32 * j + lane))] = r[j];
        __syncwarp();

        size_t base = (size_t)f * NPAIR;
#pragma unroll
        for (int u = 0; u < 5; u++) {
            int k = (u < 4) ? 32 * u + lane : 128;
            bool active = (u < 4) || (lane == 0);
            if (active) {
                float2 zk = Zs[SWZ(k)];
                float2 zm = Zs[SWZ((256 - k) & 255)];
                float2 E = make_float2(0.5f * (zk.x + zm.x), 0.5f * (zk.y - zm.y));
                float2 d = make_float2(0.5f * (zk.x - zm.x), 0.5f * (zk.y + zm.y));
                float2 mid = make_float2(d.y, -d.x);          // -i * d
                float2 P = cmul(sm->W[k], mid);
                g_pair[base + k] = make_float4(E.x, E.y, P.x, P.y);
                float ax = E.x + P.x, ay = E.y + P.y;
                float bx = E.x - P.x, by = E.y - P.y;
                rA[u] = fmaxf(DECAYF * rA[u], sqrtf(ax * ax + ay * ay));
                rB[u] = fmaxf(DECAYF * rB[u], sqrtf(bx * bx + by * by));
            }
        }
        __syncwarp();
    }
    // write subchunk summaries (always, even for idle warps -> zeros)
#pragma unroll
    for (int u = 0; u < 5; u++) {
        int k = (u < 4) ? 32 * u + lane : 128;
        bool active = (u < 4) || (lane == 0);
        if (active) {
            float2 s = make_float2(rA[u], rB[u]);
            sm->subP[w][k] = s;
            g_subP[(b * NWARP + w) * NPAIR + k] = s;
        }
    }
    __syncthreads();
    // block summary over 16 subchunks (float view width 2*NPAIR = 258)
    if (t < 2 * NPAIR) {
        float D4 = g_D4;
        const float* subF = (const float*)sm->subP;
        float B = 0.0f;
#pragma unroll
        for (int j = 0; j < NWARP; j++) B = fmaxf(D4 * B, subF[j * 2 * NPAIR + t]);
        ((float*)g_blkP)[b * 2 * NPAIR + t] = B;
    }
}

// ---------------- 3-level cross-block scan ----------------
__global__ __launch_bounds__(288) void midscanA() {
    int t = threadIdx.x;
    if (t >= 2 * NPAIR) return;
    int s = blockIdx.x;
    const float* blkF = (const float*)g_blkP;
    float D64 = g_D64;
    float v[SUPLEN];
#pragma unroll
    for (int j = 0; j < SUPLEN; j++) v[j] = blkF[(s * SUPLEN + j) * 2 * NPAIR + t];
    float carry = 0.0f;
#pragma unroll
    for (int j = 0; j < SUPLEN; j++) carry = fmaxf(D64 * carry, v[j]);
    ((float*)g_supP)[s * 2 * NPAIR + t] = carry;
}

__global__ __launch_bounds__(288) void midscanB() {
    int t = threadIdx.x;
    if (t >= 2 * NPAIR) return;
    const float* supF = (const float*)g_supP;
    float D1600 = g_D1600;
    float v[NSUP];
#pragma unroll
    for (int s = 0; s < NSUP; s++) v[s] = supF[s * 2 * NPAIR + t];
    float carry = 0.0f;
#pragma unroll
    for (int s = 0; s < NSUP; s++) {
        ((float*)g_supprefP)[s * 2 * NPAIR + t] = carry;
        carry = fmaxf(D1600 * carry, v[s]);
    }
}

__global__ __launch_bounds__(288) void midscanC() {
    int t = threadIdx.x;
    if (t >= 2 * NPAIR) return;
    int s = blockIdx.x;
    const float* blkF = (const float*)g_blkP;
    float D64 = g_D64;
    float v[SUPLEN];
#pragma unroll
    for (int j = 0; j < SUPLEN; j++) v[j] = blkF[(s * SUPLEN + j) * 2 * NPAIR + t];
    float carry = ((const float*)g_supprefP)[s * 2 * NPAIR + t];
#pragma unroll
    for (int j = 0; j < SUPLEN; j++) {
        ((float*)g_blkprefP)[(s * SUPLEN + j) * 2 * NPAIR + t] = carry;
        carry = fmaxf(D64 * carry, v[j]);
    }
}

// ---------------- phase B: load pairs, gain+repack in regs, inverse FFT, OLA ----------------
__global__ __launch_bounds__(512, 2) void phaseB(float* __restrict__ out) {
    extern __shared__ char raw[];
    SmemB* sm = (SmemB*)raw;
    int t = threadIdx.x, lane = t & 31, w = t >> 5, b = blockIdx.x;
    sm->W[t] = g_W512[t];
    if (t < 256) sm->win2[t] = make_float2(g_win[2 * t], g_win[2 * t + 1]);
    for (int i = t; i < NWARP * (ACC_SPAN / 2); i += 512)
        ((float2*)sm->acc)[i] = make_float2(0.0f, 0.0f);
    __syncthreads();

    float2* Zs = sm->Z[w];
    float D4 = g_D4;
    float rA[5], rB[5];
    // per-warp exclusive prefix: block prefix + earlier warps' subchunk summaries (L2-hot)
#pragma unroll
    for (int u = 0; u < 5; u++) {
        int k = (u < 4) ? 32 * u + lane : 128;
        bool active = (u < 4) || (lane == 0);
        float2 p = make_float2(0.0f, 0.0f);
        if (active) {
            p = g_blkprefP[b * NPAIR + k];
            for (int j = 0; j < w; j++) {
                float2 sv = g_subP[(b * NWARP + j) * NPAIR + k];
                p.x = fmaxf(D4 * p.x, sv.x);
                p.y = fmaxf(D4 * p.y, sv.y);
            }
        }
        rA[u] = p.x; rB[u] = p.y;
    }

    int f0 = b * FPB + w * SUBF;
    const float scale = 1.0f / 256.0f;
    for (int i = 0; i < SUBF; i++) {
        int f = f0 + i;
        if (f >= NFRAMES) break;
        size_t base = (size_t)f * NPAIR;

        // load pair data first (MLP), then process
        float4 c[5];
#pragma unroll
        for (int u = 0; u < 5; u++) {
            int k = (u < 4) ? 32 * u + lane : 128;
            bool active = (u < 4) || (lane == 0);
            if (active) c[u] = g_pair[base + k];
        }

#pragma unroll
        for (int u = 0; u < 5; u++) {
            int k = (u < 4) ? 32 * u + lane : 128;
            bool active = (u < 4) || (lane == 0);
            if (active) {
                float2 E = make_float2(c[u].x, c[u].y);
                float2 P = make_float2(c[u].z, c[u].w);
                float ax = E.x + P.x, ay = E.y + P.y;
                float bx = E.x - P.x, by = E.y - P.y;
                float ma2 = ax * ax + ay * ay;
                float mb2 = bx * bx + by * by;
                float ra = fmaxf(DECAYF * rA[u], sqrtf(ma2)); rA[u] = ra;
                float rb = fmaxf(DECAYF * rB[u], sqrtf(mb2)); rB[u] = rb;
                float ga = ma2 / (fmaxf(0.5f * ra * ra, 1e-8f) + ma2);
                float gb = mb2 / (fmaxf(0.5f * rb * rb, 1e-8f) + mb2);
                float s = 0.5f * (ga + gb), md = 0.5f * (ga - gb);
                float2 ze = make_float2(s * E.x + md * P.x, s * E.y + md * P.y);
                float2 d2 = make_float2(md * E.x + s * P.x, md * E.y + s * P.y);
                float2 tw = sm->W[k];
                // zo = conj(W^k) * d2
                float2 zo = make_float2(tw.x * d2.x + tw.y * d2.y,
                                        tw.x * d2.y - tw.y * d2.x);
                // V[k] = conj(ze + i*zo); V[256-k] = ze - i*zo
                Zs[SWZ(k)] = make_float2(ze.x - zo.y, -(ze.y + zo.x));
                if (k >= 1 && k <= 127)
                    Zs[SWZ(256 - k)] = make_float2(ze.x + zo.y, ze.y - zo.x);
            }
        }
        __syncwarp();

        float2 r[8];
#pragma unroll
        for (int j = 0; j < 8; j++) r[j] = Zs[SWZ(32 * j + lane)];
        warp_fft256(r, lane, sm->W);

        // stage time-domain pairs into Z (swizzled scatter, conflict-free)
#pragma unroll
        for (int j = 0; j < 8; j++) {
            int pos = brev8(32 * j + lane);
            Zs[SWZ(pos)] = make_float2(r[j].x, -r[j].y);
        }
        __syncwarp();

        // linear window+scale+accumulate into warp-private OLA buffer
        float2* acc2 = sm->acc[w] + i * (HOP / 2);
#pragma unroll
        for (int j = 0; j < 8; j++) {
            int p = 32 * j + lane;
            float2 v = Zs[SWZ(p)];
            float2 w2 = sm->win2[p];
            float2 cur = acc2[p];
            cur.x = fmaf(v.x * scale, w2.x, cur.x);
            cur.y = fmaf(v.y * scale, w2.y, cur.y);
            acc2[p] = cur;
        }
        __syncwarp();
    }
    __syncthreads();

    // combine warp regions & write normalized interior output.
    // Interior: exactly 4 overlapping Hann frames -> sum win^2 = 1.5.
    const float INV_NORM = 1.0f / 1.5f;
    int t0 = b * BLK_SPAN;
    const float* accf = (const float*)sm->acc;
    for (int s = t; s < BLK_SPAN; s += 512) {
        int wo = s >> 9;          // 512 samples per warp region
        int off = s & 511;
        float val = accf[wo * ACC_SPAN + off];
        if (off < OVER && wo > 0) val += accf[(wo - 1) * ACC_SPAN + 512 + off];
        if (s < OVER) {
            g_head[b * OVER + s] = val;
        } else {
            int tt = t0 + s;
            if (tt >= PAD && tt < PAD + T_SAMPLES) out[tt - PAD] = val * INV_NORM;
        }
    }
    if (t < OVER) g_tail[b * OVER + t] = accf[(NWARP - 1) * ACC_SPAN + 512 + t];
}

// ---------------- fixup: block-boundary samples (general win^2 loop) ----------------
__global__ __launch_bounds__(384) void fixup(float* __restrict__ out) {
    int b = blockIdx.x;
    int i = threadIdx.x;
    int tt = b * BLK_SPAN + i;
    float val = g_head[b * OVER + i] + (b > 0 ? g_tail[(b - 1) * OVER + i] : 0.0f);
    if (tt >= PAD && tt < PAD + T_SAMPLES) {
        int fmax_ = tt >> 7; if (fmax_ > NFRAMES - 1) fmax_ = NFRAMES - 1;
        int fmin_ = (tt - OVER) >> 7; if (fmin_ < 0) fmin_ = 0;
        float ws = 0.0f;
        for (int fr = fmin_; fr <= fmax_; fr++) {
            float wv = g_win[tt - (fr << 7)];
            ws += wv * wv;
        }
        out[tt - PAD] = val / fmaxf(ws, 1e-11f);
    }
}

// ---------------- launch ----------------
extern "C" void kernel_launch(void* const* d_in, const int* in_sizes, int n_in,
                              void* d_out, int out_size) {
    const float* x = (const float*)d_in[0];
    float* out = (float*)d_out;

    static bool attr_done = false;
    if (!attr_done) {
        cudaFuncSetAttribute(phaseA, cudaFuncAttributeMaxDynamicSharedMemorySize,
                             (int)sizeof(SmemA));
        cudaFuncSetAttribute(phaseB, cudaFuncAttributeMaxDynamicSharedMemorySize,
                             (int)sizeof(SmemB));
        attr_done = true;
    }

    init_tables<<<1, 512>>>();
    phaseA<<<NBLKS, 512, sizeof(SmemA)>>>(x);
    midscanA<<<NSUP, 288>>>();
    midscanB<<<1, 288>>>();
    midscanC<<<NSUP, 288>>>();
    phaseB<<<NBLKS, 512, sizeof(SmemB)>>>(out);
    fixup<<<NBLKS, 384>>>(out);
}